// round 13
// baseline (speedup 1.0000x reference)
#include <cuda_runtime.h>
#include <cuda_bf16.h>
#include <math.h>
#include <stdint.h>

#define NN 50000
#define EE 400000
#define FF 128
#define F3 384
#define NRBF 20
#define EPAD (EE + NN)
#define EP 450560
#define NTILE 391                 // ceil(50000/128)
#define ROWS_PAD (NTILE * 128)    // 50048
#define SMEM_U32 26112            // 2*(128*68) + 2*(64*68)
#define SMEM_B (SMEM_U32 * 4)     // 104448 bytes

typedef unsigned long long u64;

// ---------------- f32x2 packed helpers ----------------
__device__ __forceinline__ u64 pk2(float a, float b) {
    u64 r; asm("mov.b64 %0,{%1,%2};" : "=l"(r) : "f"(a), "f"(b)); return r;
}
__device__ __forceinline__ u64 pkdup(float a) {
    u64 r; asm("mov.b64 %0,{%1,%1};" : "=l"(r) : "f"(a)); return r;
}
__device__ __forceinline__ float2 upk(u64 v) {
    float2 f; asm("mov.b64 {%0,%1},%2;" : "=f"(f.x), "=f"(f.y) : "l"(v)); return f;
}
__device__ __forceinline__ u64 f2fma(u64 a, u64 b, u64 c) {
    u64 d; asm("fma.rn.f32x2 %0,%1,%2,%3;" : "=l"(d) : "l"(a), "l"(b), "l"(c)); return d;
}
__device__ __forceinline__ u64 f2add(u64 a, u64 b) {
    u64 d; asm("add.rn.f32x2 %0,%1,%2;" : "=l"(d) : "l"(a), "l"(b)); return d;
}

// ---------------- bf16 helpers ----------------
__device__ __forceinline__ uint32_t pack_bf2(__nv_bfloat16 lo, __nv_bfloat16 hi) {
    return ((uint32_t)__bfloat16_as_ushort(hi) << 16) | (uint32_t)__bfloat16_as_ushort(lo);
}
__device__ __forceinline__ void split2_pack(float v0, float v1, uint32_t& uh, uint32_t& ul) {
    __nv_bfloat16 h0 = __float2bfloat16(v0);
    __nv_bfloat16 h1 = __float2bfloat16(v1);
    __nv_bfloat16 l0 = __float2bfloat16(v0 - __bfloat162float(h0));
    __nv_bfloat16 l1 = __float2bfloat16(v1 - __bfloat162float(h1));
    uh = pack_bf2(h0, h1);
    ul = pack_bf2(l0, l1);
}
__device__ __forceinline__ void mma_bf16(float c[4], const uint32_t a[4],
                                         uint32_t b0, uint32_t b1) {
    asm volatile("mma.sync.aligned.m16n8k16.row.col.f32.bf16.bf16.f32 "
                 "{%0,%1,%2,%3},{%4,%5,%6,%7},{%8,%9},{%0,%1,%2,%3};"
                 : "+f"(c[0]), "+f"(c[1]), "+f"(c[2]), "+f"(c[3])
                 : "r"(a[0]), "r"(a[1]), "r"(a[2]), "r"(a[3]), "r"(b0), "r"(b1));
}

// ---------------- scratch ----------------
__device__ float g_phi[NN * F3];
__device__ float g_rbf[NRBF * EP];
__device__ float g_dirx[EP];
__device__ float g_diry[EP];
__device__ float g_dirz[EP];
__device__ int   g_cnt[NN];
__device__ int   g_off[NN];
__device__ int   g_cur[NN];
__device__ int   g_order[EPAD];
__device__ uint32_t g_s2H[ROWS_PAD * 64];
__device__ uint32_t g_s2L[ROWS_PAD * 64];
__device__ uint32_t g_h2H[ROWS_PAD * 64];
__device__ uint32_t g_h2L[ROWS_PAD * 64];
__device__ uint32_t g_w1H2[FF * 64];
__device__ uint32_t g_w1L2[FF * 64];
__device__ uint32_t g_w2H2[F3 * 64];
__device__ uint32_t g_w2L2[F3 * 64];

// ---------------- GEMM body (3xBF16 mma.sync, whole-K staged once) ----------------
template <bool SILU, bool OUTBF16, int NJ>
__device__ __forceinline__ void gemm_body(int tile, int bx,
                                          const uint32_t* __restrict__ A2H,
                                          const uint32_t* __restrict__ A2L,
                                          const uint32_t* __restrict__ B2H,
                                          const uint32_t* __restrict__ B2L,
                                          const float* __restrict__ bias,
                                          uint32_t* __restrict__ OH,
                                          uint32_t* __restrict__ OL,
                                          float* __restrict__ PHI,
                                          int outN, int M,
                                          uint32_t* smem) {
    uint32_t* sAh = smem;
    uint32_t* sAl = smem + 8704;
    uint32_t* sBh = smem + 17408;
    uint32_t* sBl = smem + 21760;

    int t = threadIdx.x;
    int lane = t & 31, wid = t >> 5;
    int warp_m = wid >> 1, warp_n = wid & 1;
    int lr = lane >> 2, lc = lane & 3;
    int rowBase = tile * 128;

    {
        const uint4* gh = (const uint4*)(A2H + (size_t)rowBase * 64);
        const uint4* gl = (const uint4*)(A2L + (size_t)rowBase * 64);
#pragma unroll
        for (int sl = t; sl < 2048; sl += 256) {
            int row = sl >> 4, q = sl & 15;
            ((uint4*)(sAh + row * 68))[q] = gh[sl];
            ((uint4*)(sAl + row * 68))[q] = gl[sl];
        }
    }

#pragma unroll
    for (int jc = 0; jc < NJ; jc++) {
        int colBase = (bx * NJ + jc) * 64;
        {
            const uint4* bh_ = (const uint4*)(B2H + (size_t)colBase * 64);
            const uint4* bl_ = (const uint4*)(B2L + (size_t)colBase * 64);
#pragma unroll
            for (int sl = t; sl < 1024; sl += 256) {
                int row = sl >> 4, q = sl & 15;
                ((uint4*)(sBh + row * 68))[q] = bh_[sl];
                ((uint4*)(sBl + row * 68))[q] = bl_[sl];
            }
        }
        __syncthreads();

        float acc[2][4][4];
#pragma unroll
        for (int i = 0; i < 2; i++)
#pragma unroll
            for (int j = 0; j < 4; j++)
#pragma unroll
                for (int q = 0; q < 4; q++) acc[i][j][q] = 0.0f;

#pragma unroll
        for (int ks = 0; ks < 8; ks++) {
            int c2 = lc + ks * 8;
            uint32_t ah[2][4], al[2][4];
#pragma unroll
            for (int i = 0; i < 2; i++) {
                int r0 = warp_m * 32 + i * 16 + lr;
                int b0 = r0 * 68;
                ah[i][0] = sAh[b0 + c2];
                ah[i][1] = sAh[b0 + 8 * 68 + c2];
                ah[i][2] = sAh[b0 + c2 + 4];
                ah[i][3] = sAh[b0 + 8 * 68 + c2 + 4];
                al[i][0] = sAl[b0 + c2];
                al[i][1] = sAl[b0 + 8 * 68 + c2];
                al[i][2] = sAl[b0 + c2 + 4];
                al[i][3] = sAl[b0 + 8 * 68 + c2 + 4];
            }
            uint32_t bh[4][2], bl[4][2];
#pragma unroll
            for (int j = 0; j < 4; j++) {
                int n0 = warp_n * 32 + j * 8 + lr;
                int bb = n0 * 68;
                bh[j][0] = sBh[bb + c2];
                bh[j][1] = sBh[bb + c2 + 4];
                bl[j][0] = sBl[bb + c2];
                bl[j][1] = sBl[bb + c2 + 4];
            }
#pragma unroll
            for (int i = 0; i < 2; i++)
#pragma unroll
                for (int j = 0; j < 4; j++) {
                    mma_bf16(acc[i][j], ah[i], bh[j][0], bh[j][1]);
                    mma_bf16(acc[i][j], ah[i], bl[j][0], bl[j][1]);
                    mma_bf16(acc[i][j], al[i], bh[j][0], bh[j][1]);
                }
        }

#pragma unroll
        for (int i = 0; i < 2; i++) {
#pragma unroll
            for (int j = 0; j < 4; j++) {
                int col0 = warp_n * 32 + j * 8 + lc * 2;
                int gcol = colBase + col0;
                float b0 = bias[gcol], b1 = bias[gcol + 1];
#pragma unroll
                for (int h = 0; h < 2; h++) {
                    int grow = rowBase + warp_m * 32 + i * 16 + lr + h * 8;
                    float v0 = acc[i][j][2 * h] + b0;
                    float v1 = acc[i][j][2 * h + 1] + b1;
                    if (SILU) {
                        v0 = v0 / (1.0f + __expf(-v0));
                        v1 = v1 / (1.0f + __expf(-v1));
                    }
                    if (OUTBF16) {
                        uint32_t uh, ul; split2_pack(v0, v1, uh, ul);
                        int oi = grow * 64 + (gcol >> 1);
                        OH[oi] = uh; OL[oi] = ul;
                    } else {
                        if (grow < M)
                            *(float2*)&PHI[(size_t)grow * outN + gcol] = make_float2(v0, v1);
                    }
                }
            }
        }
        __syncthreads();
    }
}

// ---------------- fused L1: prepS | init | prepW ----------------
#define NB_PREPS 12512    // ROWS_PAD*64/256
#define NB_INIT  1759     // ceil(EPAD/256)
#define NB_PREPW 128      // (FF+F3)*64/256
__global__ void __launch_bounds__(256) k_L1(const float* __restrict__ s,
                                            const float* __restrict__ W1,
                                            const float* __restrict__ W2) {
    int b = blockIdx.x, t = threadIdx.x;
    if (b < NB_PREPS) {
        int idx = b * 256 + t;
        int row = idx >> 6, p = idx & 63;
        float v0 = 0.f, v1 = 0.f;
        if (row < NN) {
            float2 q = *(const float2*)&s[row * FF + 2 * p];
            v0 = q.x; v1 = q.y;
        }
        uint32_t uh, ul; split2_pack(v0, v1, uh, ul);
        g_s2H[idx] = uh; g_s2L[idx] = ul;
    } else if (b < NB_PREPS + NB_INIT) {
        int i = (b - NB_PREPS) * 256 + t;
        if (i < NN) g_cnt[i] = 0;
        if (i < EPAD) g_order[i] = -1;
    } else {
        int idx = (b - NB_PREPS - NB_INIT) * 256 + t;
        if (idx < FF * 64) {
            int n = idx >> 6, p = idx & 63;
            float v0 = W1[(2 * p) * FF + n];
            float v1 = W1[(2 * p + 1) * FF + n];
            uint32_t uh, ul; split2_pack(v0, v1, uh, ul);
            g_w1H2[idx] = uh; g_w1L2[idx] = ul;
        } else if (idx < (FF + F3) * 64) {
            int r2 = idx - FF * 64;
            int n = r2 >> 6, p = r2 & 63;
            float v0 = W2[(2 * p) * F3 + n];
            float v1 = W2[(2 * p + 1) * F3 + n];
            uint32_t uh, ul; split2_pack(v0, v1, uh, ul);
            g_w2H2[r2] = uh; g_w2L2[r2] = ul;
        }
    }
}

// ---------------- fused L2: gemm1 | hist ----------------
__global__ void __launch_bounds__(256) k_L2(const uint32_t* __restrict__ sH,
                                            const uint32_t* __restrict__ sL,
                                            const uint32_t* __restrict__ w1H,
                                            const uint32_t* __restrict__ w1L,
                                            const float* __restrict__ b1,
                                            uint32_t* __restrict__ hH,
                                            uint32_t* __restrict__ hL,
                                            const float* __restrict__ r) {
    extern __shared__ __align__(16) uint32_t smem[];
    int b = blockIdx.x;
    if (b < NTILE) {
        gemm_body<true, true, 2>(b, 0, sH, sL, w1H, w1L, b1, hH, hL,
                                 nullptr, 0, NN, smem);
    } else {
        int e = (b - NTILE) * 256 + threadIdx.x;
        if (e < EE) {
            int jn = (int)r[e * 5 + 1];
            atomicAdd(&g_cnt[jn], 1);
        }
    }
}

// ---------------- fused L3: scan | gemm2 (bx=0) ----------------
__global__ void __launch_bounds__(256) k_L3(const uint32_t* __restrict__ hH,
                                            const uint32_t* __restrict__ hL,
                                            const uint32_t* __restrict__ w2H,
                                            const uint32_t* __restrict__ w2L,
                                            const float* __restrict__ b2,
                                            float* __restrict__ pphi) {
    extern __shared__ __align__(16) uint32_t smem[];
    int b = blockIdx.x, t = threadIdx.x;
    if (b == 0) {
        int* part = (int*)smem;
        const int CH = (NN + 255) / 256;   // 196
        int base = t * CH, sum = 0;
        for (int i = 0; i < CH; i++) {
            int idx = base + i;
            if (idx < NN) sum += (g_cnt[idx] + 1) & ~1;
        }
        part[t] = sum;
        __syncthreads();
        for (int off = 1; off < 256; off <<= 1) {
            int v = (t >= off) ? part[t - off] : 0;
            __syncthreads();
            part[t] += v;
            __syncthreads();
        }
        int run = (t > 0) ? part[t - 1] : 0;
        for (int i = 0; i < CH; i++) {
            int idx = base + i;
            if (idx < NN) {
                g_off[idx] = run;
                g_cur[idx] = run;
                run += (g_cnt[idx] + 1) & ~1;
            }
        }
    } else {
        gemm_body<false, false, 3>(b - 1, 0, hH, hL, w2H, w2L, b2,
                                   nullptr, nullptr, pphi, F3, NN, smem);
    }
}

// ---------------- fused L4: gemm2 (bx=1) | fill ----------------
__global__ void __launch_bounds__(256) k_L4(const uint32_t* __restrict__ hH,
                                            const uint32_t* __restrict__ hL,
                                            const uint32_t* __restrict__ w2H,
                                            const uint32_t* __restrict__ w2L,
                                            const float* __restrict__ b2,
                                            float* __restrict__ pphi,
                                            const float* __restrict__ r) {
    extern __shared__ __align__(16) uint32_t smem[];
    int b = blockIdx.x;
    if (b < NTILE) {
        gemm_body<false, false, 3>(b, 1, hH, hL, w2H, w2L, b2,
                                   nullptr, nullptr, pphi, F3, NN, smem);
    } else {
        int e = (b - NTILE) * 256 + threadIdx.x;
        if (e < EE) {
            int jn = (int)r[e * 5 + 1];
            int pos = atomicAdd(&g_cur[jn], 1);
            g_order[pos] = e;
        }
    }
}

// ---------------- sort ----------------
__global__ void k_sortlists() {
    int n = blockIdx.x * blockDim.x + threadIdx.x;
    if (n >= NN) return;
    int s0 = g_off[n], s1 = s0 + g_cnt[n];
    for (int i = s0 + 1; i < s1; i++) {
        int key = g_order[i];
        int jj = i - 1;
        while (jj >= s0 && g_order[jj] > key) {
            g_order[jj + 1] = g_order[jj];
            jj--;
        }
        g_order[jj + 1] = key;
    }
}

// ---------------- per-edge precompute ----------------
__global__ void k_edge(const float* __restrict__ r) {
    int p = blockIdx.x * blockDim.x + threadIdx.x;
    if (p >= EPAD) return;
    int eid = g_order[p];
    if (eid < 0) {
#pragma unroll
        for (int k = 0; k < NRBF; k++) g_rbf[k * EP + p] = 0.0f;
        g_dirx[p] = 0.0f; g_diry[p] = 0.0f; g_dirz[p] = 0.0f;
        return;
    }
    float rx = r[eid * 5 + 2];
    float ry = r[eid * 5 + 3];
    float rz = r[eid * 5 + 4];
    float z = fabsf(rz);
    float inv = 1.0f / (z + 1e-8f);
    float th = 0.6283185307179586f * z;
    float s, c;
    sincosf(th, &s, &c);
    float twoc = 2.0f * c;
    float skm = 0.0f, sk = s;
#pragma unroll
    for (int k = 0; k < NRBF; k++) {
        g_rbf[k * EP + p] = sk * inv;
        float nxt = fmaf(twoc, sk, -skm);
        skm = sk; sk = nxt;
    }
    float nrm = sqrtf(rx * rx + ry * ry + rz * rz);
    float invn = 1.0f / (nrm + 1e-8f);
    g_dirx[p] = rx * invn;
    g_diry[p] = ry * invn;
    g_dirz[p] = rz * invn;
}

// ---------------- cutoff via MUFU ----------------
__device__ __forceinline__ float cw(float x) {
    float c = __cosf(x * 0.6283185307179586f);
    float w = fmaf(c, 0.5f, 0.5f);
    return (x < 5.0f) ? w : 0.0f;
}

// ---------------- main per-node kernel: register-prefetch chunk pipeline ----------------
__global__ void __launch_bounds__(128) k_main(const float* __restrict__ v,
                                              const float* __restrict__ Wr,
                                              const float* __restrict__ br,
                                              float* __restrict__ out) {
    __shared__ u64 sm[2][23][8];
    int t = threadIdx.x;

    u64 wr0d[NRBF], wr1d[NRBF], wr2d[NRBF];
#pragma unroll
    for (int k = 0; k < NRBF; k++) {
        wr0d[k] = pkdup(Wr[k * F3 + t]);
        wr1d[k] = pkdup(Wr[k * F3 + FF + t]);
        wr2d[k] = pkdup(Wr[k * F3 + 2 * FF + t]);
    }
    u64 br0d = pkdup(br[t]), br1d = pkdup(br[FF + t]), br2d = pkdup(br[2 * FF + t]);

    int jr0 = t >> 3, i0x = t & 7;
    int jr1 = (t + 128) >> 3, i1x = (t + 128) & 7;
    const float* rowbase0 =
        (jr0 < NRBF) ? (g_rbf + jr0 * EP) :
        (jr0 == 20) ? g_dirx : (jr0 == 21) ? g_diry : g_dirz;
    const float* rowbase1 =
        (jr1 < NRBF) ? (g_rbf + jr1 * EP) :
        (jr1 == 20) ? g_dirx : (jr1 == 21) ? g_diry : g_dirz;
    bool has2 = (t < 56);

    int cur_n = blockIdx.x;
    if (cur_n >= NN) return;
    int cur_c = 0;
    int cur_cnt = g_cnt[cur_n];
    int cur_base = g_off[cur_n];

    u64 pr0, pr1 = 0ull;
    {
        int pbase = cur_base;
        pr0 = *(const u64*)(rowbase0 + pbase + (i0x << 1));
        if (has2) pr1 = *(const u64*)(rowbase1 + pbase + (i1x << 1));
    }

    u64 accA = 0ull, accB = 0ull, bx = 0ull, by = 0ull, bz = 0ull;
    int buf = 0;

    while (true) {
        u64* dst = &sm[buf][0][0];
        dst[t] = pr0;
        if (has2) dst[t + 128] = pr1;

        int npairs = (cur_cnt + 1) >> 1;
        int nchunks = (npairs + 7) >> 3;
        bool last_of_node = (cur_c + 1 >= nchunks);
        int nxt_n, nxt_c, nxt_cnt = 0, nxt_base = 0;
        if (!last_of_node) {
            nxt_n = cur_n; nxt_c = cur_c + 1; nxt_cnt = cur_cnt; nxt_base = cur_base;
        } else {
            nxt_n = cur_n + gridDim.x; nxt_c = 0;
            if (nxt_n < NN) {
                nxt_cnt = g_cnt[nxt_n];
                nxt_base = g_off[nxt_n];
            }
        }
        if (nxt_n < NN) {
            int pbase = nxt_base + (nxt_c << 4);
            pr0 = *(const u64*)(rowbase0 + pbase + (i0x << 1));
            if (has2) pr1 = *(const u64*)(rowbase1 + pbase + (i1x << 1));
        }
        __syncthreads();

        int pi0 = cur_c << 3;
        int nc = npairs - pi0; if (nc > 8) nc = 8; if (nc < 0) nc = 0;
        for (int i = 0; i < nc; i++) {
            u64 x0 = br0d, x1 = br1d, x2 = br2d;
#pragma unroll
            for (int k = 0; k < NRBF; k++) {
                u64 rr = sm[buf][k][i];
                x0 = f2fma(rr, wr0d[k], x0);
                x1 = f2fma(rr, wr1d[k], x1);
                x2 = f2fma(rr, wr2d[k], x2);
            }
            float2 v0 = upk(x0), v1 = upk(x1), v2 = upk(x2);
            u64 W0 = pk2(cw(v0.x), cw(v0.y));
            u64 W1v = pk2(cw(v1.x), cw(v1.y));
            u64 W2v = pk2(cw(v2.x), cw(v2.y));
            u64 m = (((pi0 + i) << 1) + 1 < cur_cnt) ? ~0ull : 0xFFFFFFFFull;
            accA = f2add(accA, W0 & m);
            accB = f2add(accB, W1v & m);
            bx = f2fma(W2v, sm[buf][20][i], bx);
            by = f2fma(W2v, sm[buf][21][i], by);
            bz = f2fma(W2v, sm[buf][22][i], bz);
        }
        buf ^= 1;

        if (last_of_node) {
            float2 rA = upk(accA), rB = upk(accB);
            float2 rx = upk(bx), ry = upk(by), rz = upk(bz);
            float a1 = rA.x + rA.y;
            float a2 = rB.x + rB.y;
            float cx = rx.x + rx.y;
            float cy = ry.x + ry.y;
            float cz = rz.x + rz.y;

            float ph1 = g_phi[cur_n * F3 + t];
            float ph2 = g_phi[cur_n * F3 + FF + t];
            float ph3 = g_phi[cur_n * F3 + 2 * FF + t];
            int nf = cur_n * FF + t;
            float vx = v[nf * 3 + 0], vy = v[nf * 3 + 1], vz = v[nf * 3 + 2];
            float s1v = ph1 * a1;
            out[nf * 3 + 0] = fmaf(vx, s1v, ph3 * cx);
            out[nf * 3 + 1] = fmaf(vy, s1v, ph3 * cy);
            out[nf * 3 + 2] = fmaf(vz, s1v, ph3 * cz);
            out[NN * F3 + nf] = ph2 * a2;
            accA = accB = bx = by = bz = 0ull;
        }

        if (nxt_n >= NN) break;
        cur_n = nxt_n; cur_c = nxt_c; cur_cnt = nxt_cnt; cur_base = nxt_base;
    }
}

// ---------------- launch ----------------
extern "C" void kernel_launch(void* const* d_in, const int* in_sizes, int n_in,
                              void* d_out, int out_size) {
    (void)in_sizes; (void)n_in; (void)out_size;
    const float* v  = (const float*)d_in[0];
    const float* s  = (const float*)d_in[1];
    const float* r  = (const float*)d_in[2];
    const float* W1 = (const float*)d_in[3];
    const float* b1 = (const float*)d_in[4];
    const float* W2 = (const float*)d_in[5];
    const float* b2 = (const float*)d_in[6];
    const float* Wr = (const float*)d_in[7];
    const float* br = (const float*)d_in[8];
    float* out = (float*)d_out;

    cudaFuncSetAttribute(k_L2, cudaFuncAttributeMaxDynamicSharedMemorySize, SMEM_B);
    cudaFuncSetAttribute(k_L3, cudaFuncAttributeMaxDynamicSharedMemorySize, SMEM_B);
    cudaFuncSetAttribute(k_L4, cudaFuncAttributeMaxDynamicSharedMemorySize, SMEM_B);

    void* q;
    uint32_t *sH, *sL, *hH, *hL, *w1H, *w1L, *w2H, *w2L;
    float* pphi;
    cudaGetSymbolAddress(&q, g_s2H);  sH  = (uint32_t*)q;
    cudaGetSymbolAddress(&q, g_s2L);  sL  = (uint32_t*)q;
    cudaGetSymbolAddress(&q, g_h2H);  hH  = (uint32_t*)q;
    cudaGetSymbolAddress(&q, g_h2L);  hL  = (uint32_t*)q;
    cudaGetSymbolAddress(&q, g_w1H2); w1H = (uint32_t*)q;
    cudaGetSymbolAddress(&q, g_w1L2); w1L = (uint32_t*)q;
    cudaGetSymbolAddress(&q, g_w2H2); w2H = (uint32_t*)q;
    cudaGetSymbolAddress(&q, g_w2L2); w2L = (uint32_t*)q;
    cudaGetSymbolAddress(&q, g_phi);  pphi = (float*)q;

    const int NB_HIST = (EE + 255) / 256;   // 1563

    // L1: prepS | init | prepW
    k_L1<<<NB_PREPS + NB_INIT + NB_PREPW, 256>>>(s, W1, W2);
    // L2: gemm1 (391) | hist (1563)
    k_L2<<<NTILE + NB_HIST, 256, SMEM_B>>>(sH, sL, w1H, w1L, b1, hH, hL, r);
    // L3: scan (1) | gemm2 bx=0 (391)
    k_L3<<<1 + NTILE, 256, SMEM_B>>>(hH, hL, w2H, w2L, b2, pphi);
    // L4: gemm2 bx=1 (391) | fill (1563)
    k_L4<<<NTILE + NB_HIST, 256, SMEM_B>>>(hH, hL, w2H, w2L, b2, pphi, r);
    // L5-L7: sort -> edge -> main
    k_sortlists<<<(NN + 127) / 128, 128>>>();
    k_edge<<<(EPAD + 127) / 128, 128>>>(r);
    k_main<<<4096, 128>>>(v, Wr, br, out);
}